// round 8
// baseline (speedup 1.0000x reference)
#include <cuda_runtime.h>

#define Hh 64
#define Tt 512
#define Bt 4096
#define BPB 30      // batches per block, grid = 137
#define NBT 10      // batches per 128-thread group
#define NTHREADS 384
#define TX 32

// SMEM float offsets
#define W_FLOATS   (3 * 2 * 8 * 64 * 4)          // 12288 floats = 48KB
#define HROW       72                             // floats per batch row (2 kh regions of 36)
#define HB_FLOATS  (2 * BPB * HROW)               // 4320
#define HB_OFF     W_FLOATS
#define XS_OFF     (W_FLOATS + HB_FLOATS)

typedef unsigned long long ull;

__device__ __forceinline__ ull ffma2(ull a, ull b, ull c) {
    ull d;
    asm("fma.rn.f32x2 %0, %1, %2, %3;" : "=l"(d) : "l"(a), "l"(b), "l"(c));
    return d;
}
__device__ __forceinline__ float2 unpk(ull v) {
    float2 f;
    asm("mov.b64 {%0, %1}, %2;" : "=f"(f.x), "=f"(f.y) : "l"(v));
    return f;
}
__device__ __forceinline__ void grpbar(int id) {
    asm volatile("bar.sync %0, 128;" :: "r"(id) : "memory");
}
__device__ __forceinline__ float sigmoid_f(float x) {
    float e = __expf(-x);
    return __fdividef(1.f, 1.f + e);
}
__device__ __forceinline__ float tanh_f(float x) {
    float e = __expf(-2.f * x);
    return __fdividef(1.f - e, 1.f + e);
}

extern "C" __global__ void __launch_bounds__(NTHREADS, 1)
gru_persistent_kernel(const float* __restrict__ x,
                      const float* __restrict__ W_ih,
                      const float* __restrict__ W_hh,
                      const float* __restrict__ b_ih,
                      const float* __restrict__ b_hh,
                      const float* __restrict__ W_out,
                      const float* __restrict__ b_out,
                      float* __restrict__ out)
{
    extern __shared__ float sm[];
    // Weights: [gate][kh][kq][j] as float4 = W_hh[(gate*64+j)*64 + kh*32 + 4kq + 0..3]
    float4* Wt4 = reinterpret_cast<float4*>(sm);
    float* hb = sm + HB_OFF;                 // [2][BPB][72]  (kh regions at +0 / +36 floats)
    float* xs = sm + XS_OFF;                 // [BPB][TX]

    const int tid  = threadIdx.x;
    const int lane = tid & 31;
    const int kh   = lane >> 4;              // k-half: 0 -> k 0..31, 1 -> k 32..63
    const int wgrp = (tid & 127) >> 5;       // warp within 128-thr group: j block
    const int j    = wgrp * 16 + (lane & 15);
    const int grp  = tid >> 7;               // 0..2
    const int lt   = tid & 127;
    const int bBase = blockIdx.x * BPB;

    // Prepack weights
    for (int idx = tid; idx < 3 * 2 * 8 * 64; idx += NTHREADS) {
        int jj = idx & 63;
        int kq = (idx >> 6) & 7;
        int khh = (idx >> 9) & 1;
        int gate = idx >> 10;
        const float* src = W_hh + (gate * Hh + jj) * Hh + khh * 32 + 4 * kq;
        Wt4[idx] = make_float4(src[0], src[1], src[2], src[3]);
    }
    for (int idx = tid; idx < HB_FLOATS; idx += NTHREADS)
        hb[idx] = 0.f;

    const float wir = W_ih[j];
    const float wiz = W_ih[Hh + j];
    const float win = W_ih[2 * Hh + j];
    const float cr  = b_ih[j]          + b_hh[j];
    const float cz  = b_ih[Hh + j]     + b_hh[Hh + j];
    const float cnx = b_ih[2 * Hh + j];
    const float cnh = b_hh[2 * Hh + j];

    __syncthreads();

    float hprev[5];
    #pragma unroll
    for (int i = 0; i < 5; ++i) hprev[i] = 0.f;

    int cur = 0;
    const int bar = grp + 1;
    const int blBase = grp * NBT;

    for (int t = 0; t < Tt; ++t) {
        if ((t & (TX - 1)) == 0) {
            // Stage x: NBT*TX = 320 floats per 128-thread group
            #pragma unroll
            for (int r = 0; r < 3; ++r) {
                int idx = lt + r * 128;
                if (idx < NBT * TX) {
                    int bi = idx >> 5;
                    int tt2 = idx & 31;
                    int bl = blBase + bi;
                    int bg = bBase + bl;
                    xs[bl * TX + tt2] = (bg < Bt) ? x[bg * Tt + t + tt2] : 0.f;
                }
            }
            grpbar(bar);
        }

        ull ar[NBT], az[NBT], an[NBT];
        #pragma unroll
        for (int i = 0; i < NBT; ++i) { ar[i] = 0ull; az[i] = 0ull; an[i] = 0ull; }

        // This thread's kh region of h for the group's batches
        const float* hrow = hb + cur * BPB * HROW + blBase * HROW + kh * 36;

        #pragma unroll
        for (int kq = 0; kq < 8; ++kq) {
            ull2_t:
            ;
            const ulonglong2 wr = *reinterpret_cast<const ulonglong2*>(
                Wt4 + ((0 * 2 + kh) * 8 + kq) * 64 + j);
            const ulonglong2 wz = *reinterpret_cast<const ulonglong2*>(
                Wt4 + ((1 * 2 + kh) * 8 + kq) * 64 + j);
            const ulonglong2 wn = *reinterpret_cast<const ulonglong2*>(
                Wt4 + ((2 * 2 + kh) * 8 + kq) * 64 + j);
            #pragma unroll
            for (int i = 0; i < NBT; ++i) {
                ulonglong2 h2 = *reinterpret_cast<const ulonglong2*>(hrow + i * HROW + kq * 4);
                ar[i] = ffma2(h2.x, wr.x, ar[i]);
                ar[i] = ffma2(h2.y, wr.y, ar[i]);
                az[i] = ffma2(h2.x, wz.x, az[i]);
                az[i] = ffma2(h2.y, wz.y, az[i]);
                an[i] = ffma2(h2.x, wn.x, an[i]);
                an[i] = ffma2(h2.y, wn.y, an[i]);
            }
        }

        // Combine k-halves with partner lane (lane ^ 16)
        float tr[NBT], tz[NBT], tn[NBT];
        #pragma unroll
        for (int i = 0; i < NBT; ++i) {
            float2 p; float s;
            p = unpk(ar[i]); s = p.x + p.y;
            tr[i] = s + __shfl_xor_sync(0xffffffffu, s, 16);
            p = unpk(az[i]); s = p.x + p.y;
            tz[i] = s + __shfl_xor_sync(0xffffffffu, s, 16);
            p = unpk(an[i]); s = p.x + p.y;
            tn[i] = s + __shfl_xor_sync(0xffffffffu, s, 16);
        }

        const int tt = t & (TX - 1);
        float* hnext = hb + (cur ^ 1) * BPB * HROW;
        const int jslot = (j >> 5) * 36 + (j & 31);

        // kh=0 lanes: batches 0..4 of group; kh=1 lanes: batches 5..9
        #pragma unroll
        for (int i = 0; i < 5; ++i) {
            const int ii = kh * 5 + i;
            const int bl = blBase + ii;
            float xv = xs[bl * TX + tt];
            float r  = sigmoid_f(fmaf(xv, wir, tr[ii] + cr));
            float z  = sigmoid_f(fmaf(xv, wiz, tz[ii] + cz));
            float n  = tanh_f(fmaf(xv, win, cnx) + r * (tn[ii] + cnh));
            float hn = fmaf(z, hprev[i] - n, n);
            hprev[i] = hn;
            hnext[bl * HROW + jslot] = hn;
        }
        grpbar(bar);
        cur ^= 1;
    }

    __syncthreads();

    if (tid < BPB && bBase + tid < Bt) {
        const float* hl = hb + cur * BPB * HROW + tid * HROW;
        float s = b_out[0];
        #pragma unroll
        for (int k = 0; k < Hh; ++k)
            s = fmaf(hl[(k >> 5) * 36 + (k & 31)], W_out[k], s);
        out[bBase + tid] = s;
    }
}

extern "C" void kernel_launch(void* const* d_in, const int* in_sizes, int n_in,
                              void* d_out, int out_size)
{
    const float* x     = (const float*)d_in[0];
    const float* W_ih  = (const float*)d_in[1];
    const float* W_hh  = (const float*)d_in[2];
    const float* b_ih  = (const float*)d_in[3];
    const float* b_hh  = (const float*)d_in[4];
    const float* W_out = (const float*)d_in[5];
    const float* b_out = (const float*)d_in[6];
    float* out = (float*)d_out;

    const size_t smem = (size_t)(W_FLOATS + HB_FLOATS + BPB * TX) * sizeof(float);
    cudaFuncSetAttribute(gru_persistent_kernel,
                         cudaFuncAttributeMaxDynamicSharedMemorySize, (int)smem);

    const int grid = (Bt + BPB - 1) / BPB;   // 137
    gru_persistent_kernel<<<grid, NTHREADS, smem>>>(
        x, W_ih, W_hh, b_ih, b_hh, W_out, b_out, out);
}

// round 9
// speedup vs baseline: 1.4324x; 1.4324x over previous
#include <cuda_runtime.h>

#define Hh 64
#define Tt 512
#define Bt 4096
#define BPB 16      // batches per block, grid = 256
#define NTHREADS 256
#define TX 32
#define HSTR 68     // h row stride in floats (272B: 4 batch rows -> distinct 16B slots)

typedef unsigned long long ull;

__device__ __forceinline__ ull ffma2(ull a, ull b, ull c) {
    ull d;
    asm("fma.rn.f32x2 %0, %1, %2, %3;" : "=l"(d) : "l"(a), "l"(b), "l"(c));
    return d;
}
__device__ __forceinline__ float2 unpk(ull v) {
    float2 f;
    asm("mov.b64 {%0, %1}, %2;" : "=f"(f.x), "=f"(f.y) : "l"(v));
    return f;
}
__device__ __forceinline__ float sigmoid_f(float x) {
    float e = __expf(-x);
    return __fdividef(1.f, 1.f + e);
}
__device__ __forceinline__ float tanh_f(float x) {
    float e = __expf(-2.f * x);
    return __fdividef(1.f - e, 1.f + e);
}

extern "C" __global__ void __launch_bounds__(NTHREADS, 2)
gru_persistent_kernel(const float* __restrict__ x,
                      const float* __restrict__ W_ih,
                      const float* __restrict__ W_hh,
                      const float* __restrict__ b_ih,
                      const float* __restrict__ b_hh,
                      const float* __restrict__ W_out,
                      const float* __restrict__ b_out,
                      float* __restrict__ out)
{
    extern __shared__ float sm[];
    // Weights: [gate][kq][j] float4 = {W_hh[(gate*64+j)*64 + 4kq .. +3]}  (48KB)
    float4* Wt4 = reinterpret_cast<float4*>(sm);
    float* hb = sm + 3 * 16 * Hh * 4;        // [2][BPB][HSTR]
    float* xs = hb + 2 * BPB * HSTR;         // [BPB][TX]

    const int tid   = threadIdx.x;
    const int lane  = tid & 31;
    const int warp  = tid >> 5;              // 0..7 -> j block
    const int jlane = lane & 7;
    const int bg    = lane >> 3;             // 0..3 batch group (4 batches each)
    const int j     = warp * 8 + jlane;
    const int bBase = blockIdx.x * BPB;

    // Prepack weights
    for (int idx = tid; idx < 3 * 16 * Hh; idx += NTHREADS) {
        int jj = idx & 63;
        int kq = (idx >> 6) & 15;
        int gate = idx >> 10;
        const float* src = W_hh + (gate * Hh + jj) * Hh + 4 * kq;
        Wt4[(gate * 16 + kq) * 64 + jj] = make_float4(src[0], src[1], src[2], src[3]);
    }
    for (int idx = tid; idx < 2 * BPB * HSTR; idx += NTHREADS)
        hb[idx] = 0.f;

    const float wir = W_ih[j];
    const float wiz = W_ih[Hh + j];
    const float win = W_ih[2 * Hh + j];
    const float cr  = b_ih[j]          + b_hh[j];
    const float cz  = b_ih[Hh + j]     + b_hh[Hh + j];
    const float cnx = b_ih[2 * Hh + j];
    const float cnh = b_hh[2 * Hh + j];

    __syncthreads();

    // Lane owns batches bg*4 .. bg*4+3 at hidden index j, full k range.
    float hprev[4];
    #pragma unroll
    for (int i = 0; i < 4; ++i) hprev[i] = 0.f;

    int cur = 0;

    for (int t = 0; t < Tt; ++t) {
        if ((t & (TX - 1)) == 0) {
            #pragma unroll
            for (int r = 0; r < 2; ++r) {
                int idx = tid + r * NTHREADS;
                int bi = idx >> 5;
                int tt2 = idx & 31;
                xs[bi * TX + tt2] = x[(bBase + bi) * Tt + t + tt2];
            }
            __syncthreads();
        }

        ull ar[4], az[4], an[4];
        #pragma unroll
        for (int i = 0; i < 4; ++i) { ar[i] = 0ull; az[i] = 0ull; an[i] = 0ull; }

        const float* hbase = hb + cur * BPB * HSTR + (bg * 4) * HSTR;

        #pragma unroll
        for (int kq = 0; kq < 16; ++kq) {
            // 8 j-lanes span 128B contiguous; bg-duplicates dedup -> 1 wavefront
            ulonglong2 wr = *reinterpret_cast<const ulonglong2*>(&Wt4[(0 * 16 + kq) * 64 + j]);
            ulonglong2 wz = *reinterpret_cast<const ulonglong2*>(&Wt4[(1 * 16 + kq) * 64 + j]);
            ulonglong2 wn = *reinterpret_cast<const ulonglong2*>(&Wt4[(2 * 16 + kq) * 64 + j]);
            #pragma unroll
            for (int i = 0; i < 4; ++i) {
                ulonglong2 h2 = *reinterpret_cast<const ulonglong2*>(hbase + i * HSTR + 4 * kq);
                ar[i] = ffma2(h2.x, wr.x, ar[i]);
                ar[i] = ffma2(h2.y, wr.y, ar[i]);
                az[i] = ffma2(h2.x, wz.x, az[i]);
                az[i] = ffma2(h2.y, wz.y, az[i]);
                an[i] = ffma2(h2.x, wn.x, an[i]);
                an[i] = ffma2(h2.y, wn.y, an[i]);
            }
        }

        const int tt = t & (TX - 1);
        float* hnext = hb + (cur ^ 1) * BPB * HSTR;
        #pragma unroll
        for (int i = 0; i < 4; ++i) {
            const int bl = bg * 4 + i;
            float2 pr = unpk(ar[i]);
            float2 pz = unpk(az[i]);
            float2 pn = unpk(an[i]);
            float sr = pr.x + pr.y;
            float sz = pz.x + pz.y;
            float sn = pn.x + pn.y;
            float xv = xs[bl * TX + tt];
            float r  = sigmoid_f(fmaf(xv, wir, sr + cr));
            float z  = sigmoid_f(fmaf(xv, wiz, sz + cz));
            float n  = tanh_f(fmaf(xv, win, cnx) + r * (sn + cnh));
            float hn = fmaf(z, hprev[i] - n, n);
            hprev[i] = hn;
            hnext[bl * HSTR + j] = hn;
        }
        __syncthreads();
        cur ^= 1;
    }

    if (tid < BPB) {
        const float* hl = hb + cur * BPB * HSTR + tid * HSTR;
        float s = b_out[0];
        #pragma unroll
        for (int k = 0; k < Hh; ++k)
            s = fmaf(hl[k], W_out[k], s);
        out[bBase + tid] = s;
    }
}

extern "C" void kernel_launch(void* const* d_in, const int* in_sizes, int n_in,
                              void* d_out, int out_size)
{
    const float* x     = (const float*)d_in[0];
    const float* W_ih  = (const float*)d_in[1];
    const float* W_hh  = (const float*)d_in[2];
    const float* b_ih  = (const float*)d_in[3];
    const float* b_hh  = (const float*)d_in[4];
    const float* W_out = (const float*)d_in[5];
    const float* b_out = (const float*)d_in[6];
    float* out = (float*)d_out;

    const size_t smem = (size_t)(3 * 16 * Hh * 4 + 2 * BPB * HSTR + BPB * TX) * sizeof(float);
    cudaFuncSetAttribute(gru_persistent_kernel,
                         cudaFuncAttributeMaxDynamicSharedMemorySize, (int)smem);

    const int grid = Bt / BPB;               // 256
    gru_persistent_kernel<<<grid, NTHREADS, smem>>>(
        x, W_ih, W_hh, b_ih, b_hh, W_out, b_out, out);
}

// round 11
// speedup vs baseline: 1.7398x; 1.2146x over previous
#include <cuda_runtime.h>

#define Hh 64
#define Tt 512
#define Bt 4096
#define BPB 15      // batches per block; grid = 274 -> 2 CTAs on most SMs
#define NBT 5       // batches per 64-thread group
#define NTHREADS 192
#define TX 32       // x timesteps staged per chunk

typedef unsigned long long ull;

__device__ __forceinline__ ull ffma2(ull a, ull b, ull c) {
    ull d;
    asm("fma.rn.f32x2 %0, %1, %2, %3;" : "=l"(d) : "l"(a), "l"(b), "l"(c));
    return d;
}
__device__ __forceinline__ float2 unpk(ull v) {
    float2 f;
    asm("mov.b64 {%0, %1}, %2;" : "=f"(f.x), "=f"(f.y) : "l"(v));
    return f;
}
__device__ __forceinline__ void grpbar(int id) {
    asm volatile("bar.sync %0, 64;" :: "r"(id) : "memory");
}
// exp-limit-safe: preacts bounded, inf/0 limits give correct saturated results
__device__ __forceinline__ float sigmoid_f(float x) {
    float e = __expf(-x);
    return __fdividef(1.f, 1.f + e);
}
__device__ __forceinline__ float tanh_f(float x) {
    float e = __expf(-2.f * x);
    return __fdividef(1.f - e, 1.f + e);
}

extern "C" __global__ void __launch_bounds__(NTHREADS, 2)
gru_persistent_kernel(const float* __restrict__ x,
                      const float* __restrict__ W_ih,
                      const float* __restrict__ W_hh,
                      const float* __restrict__ b_ih,
                      const float* __restrict__ b_hh,
                      const float* __restrict__ W_out,
                      const float* __restrict__ b_out,
                      float* __restrict__ out)
{
    extern __shared__ float sm[];
    // Weights packed as [gate][kq][j] float4 = {W[4kq..4kq+3][j]}; 48KB
    ulonglong2* W4 = reinterpret_cast<ulonglong2*>(sm);
    float* hb = sm + 3 * 16 * Hh * 4;        // [2][BPB][64]
    float* xs = hb + 2 * BPB * Hh;           // [BPB][TX]

    const int tid = threadIdx.x;
    const int j = tid & 63;
    const int g = tid >> 6;                  // 0..2 group (2 warps each)
    const int lt = tid & 63;
    const int bBase = blockIdx.x * BPB;

    // Prepack W_hh: W4f[gate*1024 + kq*64 + j] = {W_hh[(gate*64+j)*64 + 4kq+0..3]}
    {
        float4* W4f = reinterpret_cast<float4*>(sm);
        for (int idx = tid; idx < 3 * 16 * Hh; idx += NTHREADS) {
            int gate = idx >> 10;
            int rem  = idx & 1023;
            int kq   = rem >> 6;
            int jj   = rem & 63;
            const float* row = W_hh + (gate * Hh + jj) * Hh + 4 * kq;
            W4f[idx] = make_float4(row[0], row[1], row[2], row[3]);
        }
    }
    for (int idx = tid; idx < BPB * Hh; idx += NTHREADS)
        hb[idx] = 0.f;

    const float wir = W_ih[j];
    const float wiz = W_ih[Hh + j];
    const float win = W_ih[2 * Hh + j];
    const float cr  = b_ih[j]          + b_hh[j];
    const float cz  = b_ih[Hh + j]     + b_hh[Hh + j];
    const float cnx = b_ih[2 * Hh + j];
    const float cnh = b_hh[2 * Hh + j];

    __syncthreads();                          // publish weights + h0

    const ulonglong2* Wr = W4 + 0 * 16 * Hh;
    const ulonglong2* Wz = W4 + 1 * 16 * Hh;
    const ulonglong2* Wn = W4 + 2 * 16 * Hh;

    float hprev[NBT];
    #pragma unroll
    for (int i = 0; i < NBT; ++i) hprev[i] = 0.f;

    int cur = 0;
    const int bar = g + 1;

    for (int t = 0; t < Tt; ++t) {
        if ((t & (TX - 1)) == 0) {
            // Stage x for this group's NBT batches: NBT*TX=160 floats / 64 threads.
            #pragma unroll
            for (int r = 0; r < (NBT * TX + 63) / 64; ++r) {
                int idx = lt + r * 64;
                if (idx < NBT * TX) {
                    int bi = idx >> 5;
                    int tt2 = idx & 31;
                    int bl = g * NBT + bi;
                    int bg = bBase + bl;
                    xs[bl * TX + tt2] = (bg < Bt) ? x[bg * Tt + t + tt2] : 0.f;
                }
            }
            grpbar(bar);
        }

        ull acc_r[NBT], acc_z[NBT], acc_n[NBT];
        #pragma unroll
        for (int i = 0; i < NBT; ++i) { acc_r[i] = 0ull; acc_z[i] = 0ull; acc_n[i] = 0ull; }

        const float* hcur = hb + cur * BPB * Hh + (g * NBT) * Hh;

        #pragma unroll
        for (int kq = 0; kq < 16; ++kq) {
            ulonglong2 wr = Wr[kq * Hh + j];
            ulonglong2 wz = Wz[kq * Hh + j];
            ulonglong2 wn = Wn[kq * Hh + j];
            #pragma unroll
            for (int i = 0; i < NBT; ++i) {
                ulonglong2 h2 = *reinterpret_cast<const ulonglong2*>(hcur + i * Hh + 4 * kq);
                acc_r[i] = ffma2(h2.x, wr.x, acc_r[i]);
                acc_r[i] = ffma2(h2.y, wr.y, acc_r[i]);
                acc_z[i] = ffma2(h2.x, wz.x, acc_z[i]);
                acc_z[i] = ffma2(h2.y, wz.y, acc_z[i]);
                acc_n[i] = ffma2(h2.x, wn.x, acc_n[i]);
                acc_n[i] = ffma2(h2.y, wn.y, acc_n[i]);
            }
        }

        const int tt = t & (TX - 1);
        float* hnext = hb + (cur ^ 1) * BPB * Hh;
        #pragma unroll
        for (int i = 0; i < NBT; ++i) {
            const int bl = g * NBT + i;
            float2 pr = unpk(acc_r[i]);
            float2 pz = unpk(acc_z[i]);
            float2 pn = unpk(acc_n[i]);
            float ar = pr.x + pr.y;
            float az = pz.x + pz.y;
            float an = pn.x + pn.y;
            float xv = xs[bl * TX + tt];
            float r  = sigmoid_f(fmaf(xv, wir, ar + cr));
            float z  = sigmoid_f(fmaf(xv, wiz, az + cz));
            float n  = tanh_f(fmaf(xv, win, cnx) + r * (an + cnh));
            float hn = fmaf(z, hprev[i] - n, n);
            hprev[i] = hn;
            hnext[bl * Hh + j] = hn;
        }
        grpbar(bar);
        cur ^= 1;
    }

    __syncthreads();

    if (tid < BPB && bBase + tid < Bt) {
        const float* hl = hb + cur * BPB * Hh + tid * Hh;
        float s = b_out[0];
        #pragma unroll
        for (int k = 0; k < Hh; ++k)
            s = fmaf(hl[k], W_out[k], s);
        out[bBase + tid] = s;
    }
}

extern "C" void kernel_launch(void* const* d_in, const int* in_sizes, int n_in,
                              void* d_out, int out_size)
{
    const float* x     = (const float*)d_in[0];
    const float* W_ih  = (const float*)d_in[1];
    const float* W_hh  = (const float*)d_in[2];
    const float* b_ih  = (const float*)d_in[3];
    const float* b_hh  = (const float*)d_in[4];
    const float* W_out = (const float*)d_in[5];
    const float* b_out = (const float*)d_in[6];
    float* out = (float*)d_out;

    const size_t smem = (size_t)(3 * 16 * Hh * 4 + 2 * BPB * Hh + BPB * TX) * sizeof(float);
    cudaFuncSetAttribute(gru_persistent_kernel,
                         cudaFuncAttributeMaxDynamicSharedMemorySize, (int)smem);

    const int grid = (Bt + BPB - 1) / BPB;   // 274 -> 2 CTAs co-resident per SM
    gru_persistent_kernel<<<grid, NTHREADS, smem>>>(
        x, W_ih, W_hh, b_ih, b_hh, W_out, b_out, out);
}

// round 13
// speedup vs baseline: 3.7889x; 2.1778x over previous
#include <cuda_runtime.h>
#include <cuda_bf16.h>
#include <cstdint>

#define Hh 64
#define Tt 512
#define Bt 4096
#define MB 32            // batches per CTA -> grid 128
#define NTHREADS 256
#define TX 32

#define ROWB 144         // h row stride bytes (72 bf16): conflict-free frag loads
#define HPLANE (MB * ROWB)       // 4608 B per plane
#define HBUF   (2 * HPLANE)      // hi+lo planes per buffer

__device__ __forceinline__ void mma_bf16(float& d0, float& d1, float& d2, float& d3,
                                         uint32_t a0, uint32_t a1, uint32_t a2, uint32_t a3,
                                         uint32_t b0, uint32_t b1)
{
    asm("mma.sync.aligned.m16n8k16.row.col.f32.bf16.bf16.f32 "
        "{%0,%1,%2,%3},{%4,%5,%6,%7},{%8,%9},{%0,%1,%2,%3};"
        : "+f"(d0), "+f"(d1), "+f"(d2), "+f"(d3)
        : "r"(a0), "r"(a1), "r"(a2), "r"(a3), "r"(b0), "r"(b1));
}
__device__ __forceinline__ uint32_t pack2(float v0, float v1) {
    __nv_bfloat16 l = __float2bfloat16(v0), h = __float2bfloat16(v1);
    return (uint32_t)__bfloat16_as_ushort(l) | ((uint32_t)__bfloat16_as_ushort(h) << 16);
}
__device__ __forceinline__ float bf16of(float v) {
    return __bfloat162float(__float2bfloat16(v));
}
__device__ __forceinline__ float sigmoid_f(float x) {
    float e = __expf(-x);
    return __fdividef(1.f, 1.f + e);
}
__device__ __forceinline__ float tanh_f(float x) {
    float e = __expf(-2.f * x);
    return __fdividef(1.f - e, 1.f + e);
}

extern "C" __global__ void __launch_bounds__(NTHREADS, 1)
gru_mma_kernel(const float* __restrict__ x,
               const float* __restrict__ W_ih,
               const float* __restrict__ W_hh,
               const float* __restrict__ b_ih,
               const float* __restrict__ b_hh,
               const float* __restrict__ W_out,
               const float* __restrict__ b_out,
               float* __restrict__ out)
{
    __shared__ __align__(16) char hraw[2 * HBUF];       // [buf][plane hi/lo][32][144B]
    __shared__ float xs[MB * 33];                       // stride 33: conflict-free
    __shared__ float hfin[MB * 66];

    const int tid  = threadIdx.x;
    const int w    = tid >> 5;            // warp 0..7 -> j-octet
    const int lane = tid & 31;
    const int r0   = lane >> 2;           // fragment row
    const int q    = lane & 3;            // fragment col pair
    const int j0   = w * 8 + q * 2;       // this lane's j columns: j0, j0+1
    const int bBase = blockIdx.x * MB;

    // ---- B fragments (weights) in registers, hi/lo split; n = gate*64 + j ----
    uint32_t Bhi[3][4][2], Blo[3][4][2];
    #pragma unroll
    for (int g = 0; g < 3; ++g) {
        const float* row = W_hh + (g * Hh + w * 8 + r0 % 8) * Hh; // placeholder, fixed below
        (void)row;
        #pragma unroll
        for (int kt = 0; kt < 4; ++kt) {
            const int n = g * Hh + w * 8 + (lane >> 2) % 8;       // lane>>2 in 0..7
            const float* rp = W_hh + n * Hh + kt * 16 + q * 2;
            float w00 = rp[0], w01 = rp[1], w10 = rp[8], w11 = rp[9];
            float h00 = bf16of(w00), h01 = bf16of(w01), h10 = bf16of(w10), h11 = bf16of(w11);
            Bhi[g][kt][0] = pack2(h00, h01);
            Bhi[g][kt][1] = pack2(h10, h11);
            Blo[g][kt][0] = pack2(w00 - h00, w01 - h01);
            Blo[g][kt][1] = pack2(w10 - h10, w11 - h11);
        }
    }

    // Per-j epilogue constants for j0 and j0+1
    float wir[2], wiz[2], win[2], cr[2], cz[2], cnx[2], cnh[2];
    #pragma unroll
    for (int jj = 0; jj < 2; ++jj) {
        int j = j0 + jj;
        wir[jj] = W_ih[j];
        wiz[jj] = W_ih[Hh + j];
        win[jj] = W_ih[2 * Hh + j];
        cr[jj]  = b_ih[j] + b_hh[j];
        cz[jj]  = b_ih[Hh + j] + b_hh[Hh + j];
        cnx[jj] = b_ih[2 * Hh + j];
        cnh[jj] = b_hh[2 * Hh + j];
    }

    // Zero h buffers (h0 = 0 in buffer 0; zero both for simplicity)
    for (int i = tid; i < (2 * HBUF) / 4; i += NTHREADS)
        reinterpret_cast<uint32_t*>(hraw)[i] = 0;

    float ho[2][2][2];    // h_old: [mt][s][jj], b = mt*16 + s*8 + r0
    #pragma unroll
    for (int a = 0; a < 2; ++a)
        #pragma unroll
        for (int b = 0; b < 2; ++b)
            #pragma unroll
            for (int c = 0; c < 2; ++c) ho[a][b][c] = 0.f;

    for (int t = 0; t < Tt; ++t) {
        __syncthreads();                  // h(t) stores (and init) visible

        if ((t & (TX - 1)) == 0) {
            #pragma unroll
            for (int r = 0; r < (MB * TX) / NTHREADS; ++r) {
                int idx = tid + r * NTHREADS;
                int bi = idx >> 5, tt2 = idx & 31;
                xs[bi * 33 + tt2] = x[(bBase + bi) * Tt + t + tt2];
            }
            __syncthreads();
        }

        // ---- A fragments (h hi/lo) from shared ----
        const char* hp = hraw + (t & 1) * HBUF;
        uint32_t Ahi[2][4][4], Alo[2][4][4];
        #pragma unroll
        for (int mt = 0; mt < 2; ++mt) {
            #pragma unroll
            for (int kt = 0; kt < 4; ++kt) {
                int base = (mt * 16 + r0) * ROWB + (kt * 16 + q * 2) * 2;
                Ahi[mt][kt][0] = *reinterpret_cast<const uint32_t*>(hp + base);
                Ahi[mt][kt][1] = *reinterpret_cast<const uint32_t*>(hp + base + 8 * ROWB);
                Ahi[mt][kt][2] = *reinterpret_cast<const uint32_t*>(hp + base + 16);
                Ahi[mt][kt][3] = *reinterpret_cast<const uint32_t*>(hp + base + 8 * ROWB + 16);
                Alo[mt][kt][0] = *reinterpret_cast<const uint32_t*>(hp + HPLANE + base);
                Alo[mt][kt][1] = *reinterpret_cast<const uint32_t*>(hp + HPLANE + base + 8 * ROWB);
                Alo[mt][kt][2] = *reinterpret_cast<const uint32_t*>(hp + HPLANE + base + 16);
                Alo[mt][kt][3] = *reinterpret_cast<const uint32_t*>(hp + HPLANE + base + 8 * ROWB + 16);
            }
        }

        // ---- MMA: acc[mt][g][4] = h·W^T (hi·hi + lo·hi + hi·lo) ----
        float acc[2][3][4];
        #pragma unroll
        for (int mt = 0; mt < 2; ++mt)
            #pragma unroll
            for (int g = 0; g < 3; ++g)
                #pragma unroll
                for (int e = 0; e < 4; ++e) acc[mt][g][e] = 0.f;

        #pragma unroll
        for (int mt = 0; mt < 2; ++mt) {
            #pragma unroll
            for (int g = 0; g < 3; ++g) {
                #pragma unroll
                for (int kt = 0; kt < 4; ++kt) {
                    mma_bf16(acc[mt][g][0], acc[mt][g][1], acc[mt][g][2], acc[mt][g][3],
                             Ahi[mt][kt][0], Ahi[mt][kt][1], Ahi[mt][kt][2], Ahi[mt][kt][3],
                             Bhi[g][kt][0], Bhi[g][kt][1]);
                    mma_bf16(acc[mt][g][0], acc[mt][g][1], acc[mt][g][2], acc[mt][g][3],
                             Alo[mt][kt][0], Alo[mt][kt][1], Alo[mt][kt][2], Alo[mt][kt][3],
                             Bhi[g][kt][0], Bhi[g][kt][1]);
                    mma_bf16(acc[mt][g][0], acc[mt][g][1], acc[mt][g][2], acc[mt][g][3],
                             Ahi[mt][kt][0], Ahi[mt][kt][1], Ahi[mt][kt][2], Ahi[mt][kt][3],
                             Blo[g][kt][0], Blo[g][kt][1]);
                }
            }
        }

        // ---- Epilogue: lane owns (b = mt*16+s*8+r0, j = j0+jj) ----
        const int tt = t & (TX - 1);
        char* hn_hi = hraw + ((t + 1) & 1) * HBUF;
        char* hn_lo = hn_hi + HPLANE;

        #pragma unroll
        for (int mt = 0; mt < 2; ++mt) {
            #pragma unroll
            for (int s = 0; s < 2; ++s) {
                const int bl = mt * 16 + s * 8 + r0;
                const float xv = xs[bl * 33 + tt];
                float hn[2];
                #pragma unroll
                for (int jj = 0; jj < 2; ++jj) {
                    const int e = s * 2 + jj;
                    float pr = acc[mt][0][e] + fmaf(xv, wir[jj], cr[jj]);
                    float pz = acc[mt][1][e] + fmaf(xv, wiz[jj], cz[jj]);
                    float r  = sigmoid_f(pr);
                    float z  = sigmoid_f(pz);
                    float pn = fmaf(r, acc[mt][2][e] + cnh[jj], fmaf(xv, win[jj], cnx[jj]));
                    float n  = tanh_f(pn);
                    float h  = fmaf(z, ho[mt][s][jj] - n, n);
                    ho[mt][s][jj] = h;
                    hn[jj] = h;
                }
                float h0h = bf16of(hn[0]), h1h = bf16of(hn[1]);
                int off = bl * ROWB + j0 * 2;
                *reinterpret_cast<uint32_t*>(hn_hi + off) = pack2(h0h, h1h);
                *reinterpret_cast<uint32_t*>(hn_lo + off) = pack2(hn[0] - h0h, hn[1] - h1h);
            }
        }
    }

    // ---- Output ----
    #pragma unroll
    for (int mt = 0; mt < 2; ++mt)
        #pragma unroll
        for (int s = 0; s < 2; ++s) {
            int bl = mt * 16 + s * 8 + r0;
            hfin[bl * 66 + j0]     = ho[mt][s][0];
            hfin[bl * 66 + j0 + 1] = ho[mt][s][1];
        }
    __syncthreads();

    if (tid < MB) {
        float sum = b_out[0];
        #pragma unroll
        for (int k = 0; k < Hh; ++k)
            sum = fmaf(hfin[tid * 66 + k], W_out[k], sum);
        out[bBase + tid] = sum;
    }
}

extern "C" void kernel_launch(void* const* d_in, const int* in_sizes, int n_in,
                              void* d_out, int out_size)
{
    const float* x     = (const float*)d_in[0];
    const float* W_ih  = (const float*)d_in[1];
    const float* W_hh  = (const float*)d_in[2];
    const float* b_ih  = (const float*)d_in[3];
    const float* b_hh  = (const float*)d_in[4];
    const float* W_out = (const float*)d_in[5];
    const float* b_out = (const float*)d_in[6];
    float* out = (float*)d_out;

    gru_mma_kernel<<<Bt / MB, NTHREADS>>>(
        x, W_ih, W_hh, b_ih, b_hh, W_out, b_out, out);
}

// round 14
// speedup vs baseline: 4.0193x; 1.0608x over previous
#include <cuda_runtime.h>
#include <cuda_bf16.h>
#include <cstdint>

#define Hh 64
#define Tt 512
#define Bt 4096
#define MB 32            // batches per CTA -> grid 128
#define NTHREADS 256
#define TX 32

#define ROWB 288         // h row stride bytes (32 k-pairs x 8B + 32 pad) -> conflict-free LDS.64
#define HP   (16 * ROWB) // one plane: 16 rows per group
#define GSTR (2 * HP)    // per-group: 2 buffers

typedef unsigned long long ull;

__device__ __forceinline__ void mma_bf16(float* d, const uint32_t* a, const uint32_t* b)
{
    asm("mma.sync.aligned.m16n8k16.row.col.f32.bf16.bf16.f32 "
        "{%0,%1,%2,%3},{%4,%5,%6,%7},{%8,%9},{%0,%1,%2,%3};"
        : "+f"(d[0]), "+f"(d[1]), "+f"(d[2]), "+f"(d[3])
        : "r"(a[0]), "r"(a[1]), "r"(a[2]), "r"(a[3]), "r"(b[0]), "r"(b[1]));
}
__device__ __forceinline__ uint32_t pack2(float v0, float v1) {
    __nv_bfloat16 l = __float2bfloat16(v0), h = __float2bfloat16(v1);
    return (uint32_t)__bfloat16_as_ushort(l) | ((uint32_t)__bfloat16_as_ushort(h) << 16);
}
__device__ __forceinline__ float bf16of(float v) {
    return __bfloat162float(__float2bfloat16(v));
}
__device__ __forceinline__ float tanha(float x) {
    float y;
    asm("tanh.approx.f32 %0, %1;" : "=f"(y) : "f"(x));
    return y;
}
__device__ __forceinline__ void grpbar(int id) {
    asm volatile("bar.sync %0, 128;" :: "r"(id) : "memory");
}

extern "C" __global__ void __launch_bounds__(NTHREADS, 1)
gru_mma_kernel(const float* __restrict__ x,
               const float* __restrict__ W_ih,
               const float* __restrict__ W_hh,
               const float* __restrict__ b_ih,
               const float* __restrict__ b_hh,
               const float* __restrict__ W_out,
               const float* __restrict__ b_out,
               float* __restrict__ out)
{
    __shared__ __align__(16) char hbuf[2 * GSTR];   // [grp][buf][16 rows][288B]
    __shared__ float xs[MB * 33];
    __shared__ float hfin[MB * 66];

    const int tid  = threadIdx.x;
    const int w    = tid >> 5;
    const int lane = tid & 31;
    const int grp  = w >> 2;             // 0/1: batches 0-15 / 16-31
    const int wg   = w & 3;              // j-range [wg*16, wg*16+16)
    const int r0   = lane >> 2;
    const int q    = lane & 3;
    const int gbase = grp * 16;
    const int lt    = tid & 127;
    const int bBase = blockIdx.x * MB;

    // ---- B fragments in registers (hi/lo): warp covers 2 n-tiles per gate ----
    uint32_t Bhi[3][2][4][2], Blo[3][2][4][2];
    #pragma unroll
    for (int g = 0; g < 3; ++g) {
        #pragma unroll
        for (int nt = 0; nt < 2; ++nt) {
            const int n = g * Hh + wg * 16 + nt * 8 + r0;
            #pragma unroll
            for (int kt = 0; kt < 4; ++kt) {
                const float* rp = W_hh + n * Hh + kt * 16 + q * 2;
                float w00 = rp[0], w01 = rp[1], w10 = rp[8], w11 = rp[9];
                float h00 = bf16of(w00), h01 = bf16of(w01);
                float h10 = bf16of(w10), h11 = bf16of(w11);
                Bhi[g][nt][kt][0] = pack2(h00, h01);
                Bhi[g][nt][kt][1] = pack2(h10, h11);
                Blo[g][nt][kt][0] = pack2(w00 - h00, w01 - h01);
                Blo[g][nt][kt][1] = pack2(w10 - h10, w11 - h11);
            }
        }
    }

    // Epilogue constants for this lane's 4 j values: m = nt*2 + jj
    float wir[4], wiz[4], win[4], cr[4], cz[4], cnx[4], cnh[4];
    #pragma unroll
    for (int m = 0; m < 4; ++m) {
        int j = wg * 16 + (m >> 1) * 8 + 2 * q + (m & 1);
        wir[m] = W_ih[j];
        wiz[m] = W_ih[Hh + j];
        win[m] = W_ih[2 * Hh + j];
        cr[m]  = b_ih[j] + b_hh[j];
        cz[m]  = b_ih[Hh + j] + b_hh[Hh + j];
        cnx[m] = b_ih[2 * Hh + j];
        cnh[m] = b_hh[2 * Hh + j];
    }

    for (int i = tid; i < (2 * GSTR) / 4; i += NTHREADS)
        reinterpret_cast<uint32_t*>(hbuf)[i] = 0;

    float ho[2][4];                       // [row s][m]
    #pragma unroll
    for (int s = 0; s < 2; ++s)
        #pragma unroll
        for (int m = 0; m < 4; ++m) ho[s][m] = 0.f;

    __syncthreads();

    const int bar = grp + 1;
    char* gh = hbuf + grp * GSTR;

    for (int t = 0; t < Tt; ++t) {
        if ((t & (TX - 1)) == 0) {
            // Group stages x for its 16 batches: 512 floats / 128 threads
            #pragma unroll
            for (int r = 0; r < 4; ++r) {
                int idx = lt + r * 128;
                int bi = idx >> 5, tt2 = idx & 31;
                int bl = gbase + bi;
                xs[bl * 33 + tt2] = x[(bBase + bl) * Tt + t + tt2];
            }
            grpbar(bar);
        }

        // ---- A fragments: 16 x LDS.64 ({hi,lo} interleaved per k-pair) ----
        const char* hp = gh + (t & 1) * HP;
        uint32_t Ahi[4][4], Alo[4][4];
        #pragma unroll
        for (int kt = 0; kt < 4; ++kt) {
            const int p0 = kt * 8 + q, p1 = p0 + 4;
            ull v0 = *reinterpret_cast<const ull*>(hp + r0 * ROWB + p0 * 8);
            ull v1 = *reinterpret_cast<const ull*>(hp + (r0 + 8) * ROWB + p0 * 8);
            ull v2 = *reinterpret_cast<const ull*>(hp + r0 * ROWB + p1 * 8);
            ull v3 = *reinterpret_cast<const ull*>(hp + (r0 + 8) * ROWB + p1 * 8);
            Ahi[kt][0] = (uint32_t)v0; Alo[kt][0] = (uint32_t)(v0 >> 32);
            Ahi[kt][1] = (uint32_t)v1; Alo[kt][1] = (uint32_t)(v1 >> 32);
            Ahi[kt][2] = (uint32_t)v2; Alo[kt][2] = (uint32_t)(v2 >> 32);
            Ahi[kt][3] = (uint32_t)v3; Alo[kt][3] = (uint32_t)(v3 >> 32);
        }

        // ---- 72 HMMA: hi*hi + lo*hi + hi*lo ----
        float acc[3][2][4];
        #pragma unroll
        for (int g = 0; g < 3; ++g)
            #pragma unroll
            for (int nt = 0; nt < 2; ++nt)
                #pragma unroll
                for (int e = 0; e < 4; ++e) acc[g][nt][e] = 0.f;

        #pragma unroll
        for (int g = 0; g < 3; ++g) {
            #pragma unroll
            for (int nt = 0; nt < 2; ++nt) {
                #pragma unroll
                for (int kt = 0; kt < 4; ++kt) {
                    mma_bf16(acc[g][nt], Ahi[kt], Bhi[g][nt][kt]);
                    mma_bf16(acc[g][nt], Alo[kt], Bhi[g][nt][kt]);
                    mma_bf16(acc[g][nt], Ahi[kt], Blo[g][nt][kt]);
                }
            }
        }

        // ---- Epilogue ----
        const int tt = t & (TX - 1);
        char* hq = gh + ((t + 1) & 1) * HP;
        #pragma unroll
        for (int s = 0; s < 2; ++s) {
            const int row = s * 8 + r0;
            const float xv = xs[(gbase + row) * 33 + tt];
            float hv[4];
            #pragma unroll
            for (int m = 0; m < 4; ++m) {
                const int nt = m >> 1;
                const int e  = s * 2 + (m & 1);
                float pr = acc[0][nt][e] + fmaf(xv, wir[m], cr[m]);
                float pz = acc[1][nt][e] + fmaf(xv, wiz[m], cz[m]);
                float r  = fmaf(0.5f, tanha(0.5f * pr), 0.5f);
                float z  = fmaf(0.5f, tanha(0.5f * pz), 0.5f);
                float pn = fmaf(r, acc[2][nt][e] + cnh[m], fmaf(xv, win[m], cnx[m]));
                float n  = tanha(pn);
                float h  = fmaf(z, ho[s][m] - n, n);
                ho[s][m] = h;
                hv[m] = h;
            }
            #pragma unroll
            for (int nt = 0; nt < 2; ++nt) {
                float a = hv[nt * 2], b = hv[nt * 2 + 1];
                float ah = bf16of(a), bh = bf16of(b);
                uint32_t hiw = pack2(ah, bh);
                uint32_t low = pack2(a - ah, b - bh);
                ull v = (ull)hiw | ((ull)low << 32);
                *reinterpret_cast<ull*>(hq + row * ROWB + (wg * 8 + q + nt * 4) * 8) = v;
            }
        }
        grpbar(bar);
    }

    // ---- Output ----
    #pragma unroll
    for (int s = 0; s < 2; ++s) {
        int bl = gbase + s * 8 + r0;
        #pragma unroll
        for (int m = 0; m < 4; ++m) {
            int j = wg * 16 + (m >> 1) * 8 + 2 * q + (m & 1);
            hfin[bl * 66 + j] = ho[s][m];
        }
    }
    __syncthreads();

    if (tid < MB) {
        float sum = b_out[0];
        #pragma unroll
        for (int k = 0; k < Hh; ++k)
            sum = fmaf(hfin[tid * 66 + k], W_out[k], sum);
        out[bBase + tid] = sum;
    }
}

extern "C" void kernel_launch(void* const* d_in, const int* in_sizes, int n_in,
                              void* d_out, int out_size)
{
    const float* x     = (const float*)d_in[0];
    const float* W_ih  = (const float*)d_in[1];
    const float* W_hh  = (const float*)d_in[2];
    const float* b_ih  = (const float*)d_in[3];
    const float* b_hh  = (const float*)d_in[4];
    const float* W_out = (const float*)d_in[5];
    const float* b_out = (const float*)d_in[6];
    float* out = (float*)d_out;

    gru_mma_kernel<<<Bt / MB, NTHREADS>>>(
        x, W_ih, W_hh, b_ih, b_hh, W_out, b_out, out);
}

// round 15
// speedup vs baseline: 4.3884x; 1.0918x over previous
#include <cuda_runtime.h>
#include <cuda_bf16.h>
#include <cstdint>

#define Hh 64
#define Tt 512
#define Bt 4096
#define MB 16            // batches per CTA -> grid 256, 2 CTAs/SM
#define NTHREADS 256
#define TX 32

#define ROWB 288         // h row stride bytes (32 j-pairs x 8B + 32 pad)
#define HP   (16 * ROWB) // one h plane (4608 B)

typedef unsigned long long ull;

__device__ __forceinline__ void mma_bf16(float* d, const uint32_t* a, const uint32_t* b)
{
    asm("mma.sync.aligned.m16n8k16.row.col.f32.bf16.bf16.f32 "
        "{%0,%1,%2,%3},{%4,%5,%6,%7},{%8,%9},{%0,%1,%2,%3};"
        : "+f"(d[0]), "+f"(d[1]), "+f"(d[2]), "+f"(d[3])
        : "r"(a[0]), "r"(a[1]), "r"(a[2]), "r"(a[3]), "r"(b[0]), "r"(b[1]));
}
__device__ __forceinline__ uint32_t pack2(float v0, float v1) {
    __nv_bfloat16 l = __float2bfloat16(v0), h = __float2bfloat16(v1);
    return (uint32_t)__bfloat16_as_ushort(l) | ((uint32_t)__bfloat16_as_ushort(h) << 16);
}
__device__ __forceinline__ float bf16of(float v) {
    return __bfloat162float(__float2bfloat16(v));
}
__device__ __forceinline__ float tanha(float x) {
    float y;
    asm("tanh.approx.f32 %0, %1;" : "=f"(y) : "f"(x));
    return y;
}

extern "C" __global__ void __launch_bounds__(NTHREADS, 2)
gru_mma_kernel(const float* __restrict__ x,
               const float* __restrict__ W_ih,
               const float* __restrict__ W_hh,
               const float* __restrict__ b_ih,
               const float* __restrict__ b_hh,
               const float* __restrict__ W_out,
               const float* __restrict__ b_out,
               float* __restrict__ out)
{
    __shared__ __align__(16) char hbuf[2 * HP];     // [buf][16 rows][288B]
    __shared__ float xs[MB * 33];
    __shared__ __align__(16) float cj[Hh * 8];      // per-j: 2 x float4
    __shared__ float hfin[MB * 66];

    const int tid  = threadIdx.x;
    const int w    = tid >> 5;            // warp 0..7 -> n-tile (8 j)
    const int lane = tid & 31;
    const int r0   = lane >> 2;
    const int q    = lane & 3;
    const int bBase = blockIdx.x * MB;

    // ---- B fragments in registers (hi/lo): 1 n-tile per gate ----
    uint32_t Bhi[3][4][2], Blo[3][4][2];
    #pragma unroll
    for (int g = 0; g < 3; ++g) {
        const int n = g * Hh + w * 8 + r0;
        #pragma unroll
        for (int kt = 0; kt < 4; ++kt) {
            const float* rp = W_hh + n * Hh + kt * 16 + q * 2;
            float w00 = rp[0], w01 = rp[1], w10 = rp[8], w11 = rp[9];
            float h00 = bf16of(w00), h01 = bf16of(w01);
            float h10 = bf16of(w10), h11 = bf16of(w11);
            Bhi[g][kt][0] = pack2(h00, h01);
            Bhi[g][kt][1] = pack2(h10, h11);
            Blo[g][kt][0] = pack2(w00 - h00, w01 - h01);
            Blo[g][kt][1] = pack2(w10 - h10, w11 - h11);
        }
    }

    // Per-j epilogue constants -> shared LUT
    if (tid < Hh) {
        int j = tid;
        cj[j * 8 + 0] = W_ih[j];
        cj[j * 8 + 1] = W_ih[Hh + j];
        cj[j * 8 + 2] = W_ih[2 * Hh + j];
        cj[j * 8 + 3] = b_ih[j] + b_hh[j];
        cj[j * 8 + 4] = b_ih[Hh + j] + b_hh[Hh + j];
        cj[j * 8 + 5] = b_ih[2 * Hh + j];
        cj[j * 8 + 6] = b_hh[2 * Hh + j];
        cj[j * 8 + 7] = 0.f;
    }
    for (int i = tid; i < (2 * HP) / 4; i += NTHREADS)
        reinterpret_cast<uint32_t*>(hbuf)[i] = 0;

    float ho[2][2];                        // [row s][m]
    ho[0][0] = ho[0][1] = ho[1][0] = ho[1][1] = 0.f;

    __syncthreads();

    for (int t = 0; t < Tt; ++t) {
        if ((t & (TX - 1)) == 0) {
            #pragma unroll
            for (int r = 0; r < (MB * TX) / NTHREADS; ++r) {
                int idx = tid + r * NTHREADS;
                int bi = idx >> 5, tt2 = idx & 31;
                xs[bi * 33 + tt2] = x[(bBase + bi) * Tt + t + tt2];
            }
            __syncthreads();
        }

        // ---- A fragments: 16 x LDS.64 ({hi,lo} interleaved per k-pair) ----
        const char* hp = hbuf + (t & 1) * HP;
        uint32_t Ahi[4][4], Alo[4][4];
        #pragma unroll
        for (int kt = 0; kt < 4; ++kt) {
            const int p0 = kt * 8 + q, p1 = p0 + 4;
            ull v0 = *reinterpret_cast<const ull*>(hp + r0 * ROWB + p0 * 8);
            ull v1 = *reinterpret_cast<const ull*>(hp + (r0 + 8) * ROWB + p0 * 8);
            ull v2 = *reinterpret_cast<const ull*>(hp + r0 * ROWB + p1 * 8);
            ull v3 = *reinterpret_cast<const ull*>(hp + (r0 + 8) * ROWB + p1 * 8);
            Ahi[kt][0] = (uint32_t)v0; Alo[kt][0] = (uint32_t)(v0 >> 32);
            Ahi[kt][1] = (uint32_t)v1; Alo[kt][1] = (uint32_t)(v1 >> 32);
            Ahi[kt][2] = (uint32_t)v2; Alo[kt][2] = (uint32_t)(v2 >> 32);
            Ahi[kt][3] = (uint32_t)v3; Alo[kt][3] = (uint32_t)(v3 >> 32);
        }

        // ---- 36 HMMA: hi*hi + lo*hi + hi*lo ----
        float acc[3][4];
        #pragma unroll
        for (int g = 0; g < 3; ++g)
            #pragma unroll
            for (int e = 0; e < 4; ++e) acc[g][e] = 0.f;

        #pragma unroll
        for (int g = 0; g < 3; ++g) {
            #pragma unroll
            for (int kt = 0; kt < 4; ++kt) {
                mma_bf16(acc[g], Ahi[kt], Bhi[g][kt]);
                mma_bf16(acc[g], Alo[kt], Bhi[g][kt]);
                mma_bf16(acc[g], Ahi[kt], Blo[g][kt]);
            }
        }

        // ---- Epilogue: lane owns rows {r0, r0+8}, j in {w*8+2q, +1} ----
        const int tt = t & (TX - 1);
        char* hq = hbuf + ((t + 1) & 1) * HP;
        #pragma unroll
        for (int s = 0; s < 2; ++s) {
            const int row = s * 8 + r0;
            const float xv = xs[row * 33 + tt];
            float hv[2];
            #pragma unroll
            for (int m = 0; m < 2; ++m) {
                const int j = w * 8 + 2 * q + m;
                const float4 c0 = *reinterpret_cast<const float4*>(cj + j * 8);
                const float4 c1 = *reinterpret_cast<const float4*>(cj + j * 8 + 4);
                const int e = s * 2 + m;
                float pr = acc[0][e] + fmaf(xv, c0.x, c0.w);
                float pz = acc[1][e] + fmaf(xv, c0.y, c1.x);
                float r  = fmaf(0.5f, tanha(0.5f * pr), 0.5f);
                float z  = fmaf(0.5f, tanha(0.5f * pz), 0.5f);
                float pn = fmaf(r, acc[2][e] + c1.z, fmaf(xv, c0.z, c1.y));
                float n  = tanha(pn);
                float h  = fmaf(z, ho[s][m] - n, n);
                ho[s][m] = h;
                hv[m] = h;
            }
            float ah = bf16of(hv[0]), bh = bf16of(hv[1]);
            ull v = (ull)pack2(ah, bh) | ((ull)pack2(hv[0] - ah, hv[1] - bh) << 32);
            *reinterpret_cast<ull*>(hq + row * ROWB + (w * 4 + q) * 8) = v;
        }
        __syncthreads();
    }

    // ---- Output ----
    #pragma unroll
    for (int s = 0; s < 2; ++s) {
        int bl = s * 8 + r0;
        #pragma unroll
        for (int m = 0; m < 2; ++m) {
            int j = w * 8 + 2 * q + m;
            hfin[bl * 66 + j] = ho[s][m];
        }
    }
    __syncthreads();

    if (tid < MB) {
        float sum = b_out[0];
        #pragma unroll
        for (int k = 0; k < Hh; ++k)
            sum = fmaf(hfin[tid * 66 + k], W_out[k], sum);
        out[bBase + tid] = sum;
    }
}

extern "C" void kernel_launch(void* const* d_in, const int* in_sizes, int n_in,
                              void* d_out, int out_size)
{
    const float* x     = (const float*)d_in[0];
    const float* W_ih  = (const float*)d_in[1];
    const float* W_hh  = (const float*)d_in[2];
    const float* b_ih  = (const float*)d_in[3];
    const float* b_hh  = (const float*)d_in[4];
    const float* W_out = (const float*)d_in[5];
    const float* b_out = (const float*)d_in[6];
    float* out = (float*)d_out;

    gru_mma_kernel<<<Bt / MB, NTHREADS>>>(
        x, W_ih, W_hh, b_ih, b_hh, W_out, b_out, out);
}